// round 11
// baseline (speedup 1.0000x reference)
#include <cuda_runtime.h>
#include <math.h>
#include <stdint.h>

// Problem shapes (fixed by the dataset)
#define B_ROWS 16384
#define DK     512
#define NKEYS  4096
#define DV     512
#define NH     32
#define TAU_MIN 0.1f
#define TAU_MAX 5.0f
#define EPSF    1e-8f

// Scratch (NEVER passed from host — device-side nullptr sentinels only)
__device__ float g_logits[(size_t)B_ROWS * NKEYS];
__device__ float g_vt[(size_t)DV * NKEYS];

// ---------------------------------------------------------------------------
// tf32 mma.sync GEMM: C[M,N] = alpha * A[M,K] @ B[N,K]^T  (A,B K-major)
// CTA tile 128x128, BK=16, 256 threads (8 warps 4x2), warp tile 32x64.
// Double-buffered smem + register prefetch of the next K-tile.
// Sentinels: A==nullptr -> g_logits, Bm==nullptr -> g_vt, C==nullptr -> g_logits.
// ---------------------------------------------------------------------------
#define BK 16
#define LDSW 20   // 16 data + 4 pad words -> conflict-free fragment loads

__device__ __forceinline__ uint32_t f2tf32(float v) {
    uint32_t r;
    asm("cvt.rna.tf32.f32 %0, %1;" : "=r"(r) : "f"(v));
    return r;
}

__device__ __forceinline__ void mma_tf32(float* c, const uint32_t* a, const uint32_t* b) {
    asm volatile(
        "mma.sync.aligned.m16n8k8.row.col.f32.tf32.tf32.f32 "
        "{%0,%1,%2,%3}, {%4,%5,%6,%7}, {%8,%9}, {%0,%1,%2,%3};"
        : "+f"(c[0]), "+f"(c[1]), "+f"(c[2]), "+f"(c[3])
        : "r"(a[0]), "r"(a[1]), "r"(a[2]), "r"(a[3]), "r"(b[0]), "r"(b[1]));
}

__device__ __forceinline__ void cvt_store4(uint32_t* p, float4 v) {
    p[0] = f2tf32(v.x); p[1] = f2tf32(v.y);
    p[2] = f2tf32(v.z); p[3] = f2tf32(v.w);
}

__global__ __launch_bounds__(256, 2) void mma_gemm_kernel(
    const float* __restrict__ A, const float* __restrict__ Bm,
    float* __restrict__ C, int K, int ldc, float alpha)
{
    if (A == nullptr)  A  = g_logits;
    if (Bm == nullptr) Bm = g_vt;
    if (C == nullptr)  C  = g_logits;

    __shared__ uint32_t As[2][128 * LDSW];
    __shared__ uint32_t Bs[2][128 * LDSW];

    const int tid  = threadIdx.x;
    const int wid  = tid >> 5;
    const int lane = tid & 31;
    const int gid  = lane >> 2;
    const int tig  = lane & 3;
    const int m0w  = (wid >> 1) * 32;
    const int n0w  = (wid & 1) * 64;
    const int bm0  = blockIdx.y * 128;
    const int bn0  = blockIdx.x * 128;

    const int grow = tid >> 2;            // 0..63
    const int gkc  = (tid & 3) * 4;       // 0,4,8,12

    const float* Ar0 = A  + (size_t)(bm0 + grow) * K + gkc;
    const float* Ar1 = Ar0 + (size_t)64 * K;
    const float* Br0 = Bm + (size_t)(bn0 + grow) * K + gkc;
    const float* Br1 = Br0 + (size_t)64 * K;

    float acc[2][8][4];
#pragma unroll
    for (int mi = 0; mi < 2; mi++)
#pragma unroll
        for (int ni = 0; ni < 8; ni++)
#pragma unroll
            for (int c = 0; c < 4; c++) acc[mi][ni][c] = 0.f;

    // prologue: tile 0 -> buffer 0
    cvt_store4(&As[0][grow * LDSW + gkc],        *(const float4*)(Ar0));
    cvt_store4(&As[0][(grow + 64) * LDSW + gkc], *(const float4*)(Ar1));
    cvt_store4(&Bs[0][grow * LDSW + gkc],        *(const float4*)(Br0));
    cvt_store4(&Bs[0][(grow + 64) * LDSW + gkc], *(const float4*)(Br1));
    __syncthreads();

    const int niter = K / BK;
    for (int it = 0; it < niter; ++it) {
        const int cur = it & 1;
        const bool has_next = (it + 1 < niter);

        // prefetch next K-tile into registers (overlaps with MMAs below)
        float4 pa0, pa1, pb0, pb1;
        if (has_next) {
            const int k1 = (it + 1) * BK;
            pa0 = *(const float4*)(Ar0 + k1);
            pa1 = *(const float4*)(Ar1 + k1);
            pb0 = *(const float4*)(Br0 + k1);
            pb1 = *(const float4*)(Br1 + k1);
        }

        // compute on current buffer
        const uint32_t* Ab = As[cur];
        const uint32_t* Bb = Bs[cur];
#pragma unroll
        for (int ks = 0; ks < 2; ks++) {
            const int kk = ks * 8 + tig;
            uint32_t a[2][4];
#pragma unroll
            for (int mi = 0; mi < 2; mi++) {
                int r = m0w + mi * 16 + gid;
                a[mi][0] = Ab[r * LDSW + kk];
                a[mi][1] = Ab[(r + 8) * LDSW + kk];
                a[mi][2] = Ab[r * LDSW + kk + 4];
                a[mi][3] = Ab[(r + 8) * LDSW + kk + 4];
            }
#pragma unroll
            for (int ni = 0; ni < 8; ni++) {
                int c = n0w + ni * 8 + gid;
                uint32_t b0 = Bb[c * LDSW + kk];
                uint32_t b1 = Bb[c * LDSW + kk + 4];
#pragma unroll
                for (int mi = 0; mi < 2; mi++) {
                    uint32_t bb[2] = {b0, b1};
                    mma_tf32(acc[mi][ni], a[mi], bb);
                }
            }
        }

        // stage prefetched tile into the other buffer
        if (has_next) {
            const int nxt = cur ^ 1;
            cvt_store4(&As[nxt][grow * LDSW + gkc],        pa0);
            cvt_store4(&As[nxt][(grow + 64) * LDSW + gkc], pa1);
            cvt_store4(&Bs[nxt][grow * LDSW + gkc],        pb0);
            cvt_store4(&Bs[nxt][(grow + 64) * LDSW + gkc], pb1);
            __syncthreads();
        }
    }

    // epilogue
#pragma unroll
    for (int mi = 0; mi < 2; mi++) {
        const int row0 = bm0 + m0w + mi * 16 + gid;
#pragma unroll
        for (int ni = 0; ni < 8; ni++) {
            const int col = bn0 + n0w + ni * 8 + tig * 2;
            float2 v0 = make_float2(alpha * acc[mi][ni][0], alpha * acc[mi][ni][1]);
            float2 v1 = make_float2(alpha * acc[mi][ni][2], alpha * acc[mi][ni][3]);
            *(float2*)&C[(size_t)row0 * ldc + col]       = v0;
            *(float2*)&C[(size_t)(row0 + 8) * ldc + col] = v1;
        }
    }
}

// ---------------------------------------------------------------------------
// V transpose: g_vt[d, n] = V[n, d]
// ---------------------------------------------------------------------------
__global__ void transpose_v_kernel(const float* __restrict__ V)
{
    __shared__ float t[32][33];
    const int n0 = blockIdx.x * 32;
    const int d0 = blockIdx.y * 32;
    const int x = threadIdx.x, y = threadIdx.y;
#pragma unroll
    for (int yy = y; yy < 32; yy += 8)
        t[yy][x] = V[(size_t)(n0 + yy) * DV + d0 + x];
    __syncthreads();
#pragma unroll
    for (int yy = y; yy < 32; yy += 8)
        g_vt[(size_t)(d0 + yy) * NKEYS + n0 + x] = t[x][yy];
}

// ---------------------------------------------------------------------------
// FUSED per-row pass: load row once into smem, online (m, Z, S) during load,
// entropy -> MLP -> tau (tid 0), then tau-softmax from smem. One logits read.
// ---------------------------------------------------------------------------
__device__ __forceinline__ void mzs_combine(float& m, float& Z, float& S,
                                            float m2, float Z2, float S2)
{
    float mn = fmaxf(m, m2);
    float e1 = __expf(m - mn);
    float e2 = __expf(m2 - mn);
    Z = Z * e1 + Z2 * e2;
    S = S * e1 + S2 * e2;
    m = mn;
}

__global__ __launch_bounds__(256) void fused_row_kernel(
    const float* __restrict__ w1, const float* __restrict__ b1,
    const float* __restrict__ w2, const float* __restrict__ b2,
    float* __restrict__ attn_out, float* __restrict__ ent_out,
    float* __restrict__ tau_out)
{
    __shared__ float sw[NKEYS];         // 16 KB row cache
    __shared__ float sred[8];
    __shared__ float sbc[2];            // broadcast: m, itau

    if (attn_out == nullptr) attn_out = g_logits;
    const int row = blockIdx.x;
    const int tid = threadIdx.x;
    const float4* c4 = (const float4*)(g_logits + (size_t)row * NKEYS);
    float4* s4 = (float4*)sw;

    // pass 1: load row into smem + online (m, Z, S)
    float m = -INFINITY, Z = 0.f, S = 0.f;
#pragma unroll
    for (int i = 0; i < 4; i++) {
        const int j = tid + i * 256;
        float4 v = c4[j];
        s4[j] = v;
        float f[4] = {v.x, v.y, v.z, v.w};
#pragma unroll
        for (int e = 0; e < 4; e++) {
            float l = f[e];
            if (l > m) {
                float sc = __expf(m - l);
                Z *= sc; S *= sc; m = l;
            }
            float ex = __expf(l - m);
            Z += ex;
            S += ex * l;
        }
    }
#pragma unroll
    for (int off = 16; off; off >>= 1) {
        float m2 = __shfl_down_sync(0xffffffffu, m, off);
        float Z2 = __shfl_down_sync(0xffffffffu, Z, off);
        float S2 = __shfl_down_sync(0xffffffffu, S, off);
        mzs_combine(m, Z, S, m2, Z2, S2);
    }
    __shared__ float smr[8], szr[8], ssr[8];
    const int wid = tid >> 5, lane = tid & 31;
    if (lane == 0) { smr[wid] = m; szr[wid] = Z; ssr[wid] = S; }
    __syncthreads();

    if (tid == 0) {
        m = smr[0]; Z = szr[0]; S = ssr[0];
#pragma unroll
        for (int w = 1; w < 8; w++) mzs_combine(m, Z, S, smr[w], szr[w], ssr[w]);

        float H = m + logf(Z) - S / Z - (float)NKEYS * EPSF;
        float max_entropy = logf((float)NKEYS);
        float e = H / (max_entropy + EPSF);
        e = fminf(fmaxf(e, 0.f), 1.f);

        float acc2 = b2[0];
#pragma unroll
        for (int h = 0; h < NH; h++) {
            float z1 = e * w1[h] + b1[h];
            float g  = 0.5f * z1 * (1.f + erff(z1 * 0.70710678118654752f));
            acc2 += g * w2[h];
        }
        float sc  = 1.f / (1.f + expf(-acc2));
        float tau = TAU_MIN + (TAU_MAX - TAU_MIN) * sc;

        if (ent_out) ent_out[row] = e;
        if (tau_out) tau_out[row] = tau;
        sbc[0] = m;
        sbc[1] = 1.f / (tau + EPSF);
    }
    __syncthreads();

    // pass 2: exp((l - m) * itau) in smem, accumulate Z2
    const float mm   = sbc[0];
    const float itau = sbc[1];
    float z = 0.f;
#pragma unroll
    for (int i = 0; i < 4; i++) {
        const int j = tid + i * 256;
        float4 v = s4[j];
        v.x = __expf((v.x - mm) * itau);
        v.y = __expf((v.y - mm) * itau);
        v.z = __expf((v.z - mm) * itau);
        v.w = __expf((v.w - mm) * itau);
        s4[j] = v;
        z += v.x + v.y + v.z + v.w;
    }
#pragma unroll
    for (int off = 16; off; off >>= 1)
        z += __shfl_down_sync(0xffffffffu, z, off);
    if (lane == 0) sred[wid] = z;
    __syncthreads();
    if (tid == 0) {
        float t = 0.f;
#pragma unroll
        for (int w = 0; w < 8; w++) t += sred[w];
        sred[0] = 1.f / t;
    }
    __syncthreads();
    const float invz = sred[0];

    // pass 3: normalized weights -> global
    float4* o4 = (float4*)(attn_out + (size_t)row * NKEYS);
#pragma unroll
    for (int i = 0; i < 4; i++) {
        const int j = tid + i * 256;
        float4 v = s4[j];
        v.x *= invz; v.y *= invz; v.z *= invz; v.w *= invz;
        o4[j] = v;
    }
}

// ---------------------------------------------------------------------------
extern "C" void kernel_launch(void* const* d_in, const int* in_sizes, int n_in,
                              void* d_out, int out_size)
{
    const float* q      = (const float*)d_in[0];
    const float* keys   = (const float*)d_in[1];
    const float* values = (const float*)d_in[2];
    const float* w1     = (const float*)d_in[3];
    const float* b1     = (const float*)d_in[4];
    const float* w2     = (const float*)d_in[5];
    const float* b2     = (const float*)d_in[6];
    float* out = (float*)d_out;

    const size_t sz_o    = (size_t)B_ROWS * DV;
    const size_t sz_attn = (size_t)B_ROWS * NKEYS;
    const size_t full_sz = sz_o + sz_attn + 2 * (size_t)B_ROWS;
    const bool full = ((size_t)out_size >= full_sz);

    float* out_o    = out;
    float* out_attn = full ? out + sz_o : nullptr;           // nullptr -> scratch
    float* out_ent  = full ? out + sz_o + sz_attn : nullptr;
    float* out_tau  = full ? out_ent + B_ROWS : nullptr;

    const float base_scale = 0.044194173824159216f;          // 512^-0.5

    // 0) transpose V -> g_vt (GEMM2's B operand)
    transpose_v_kernel<<<dim3(NKEYS / 32, DV / 32), dim3(32, 8)>>>(values);

    // 1) scaled logits -> g_logits
    mma_gemm_kernel<<<dim3(NKEYS / 128, B_ROWS / 128), 256>>>(
        q, keys, /*C=*/nullptr, DK, NKEYS, base_scale);

    // 2+3) fused: entropy + tau + tau-softmax (one logits read)
    fused_row_kernel<<<B_ROWS, 256>>>(w1, b1, w2, b2, out_attn, out_ent, out_tau);

    // 4) output = attn @ values
    const float* attn_src = full ? out_attn : nullptr;       // nullptr -> scratch
    mma_gemm_kernel<<<dim3(DV / 128, B_ROWS / 128), 256>>>(
        attn_src, /*Bm=*/nullptr, out_o, NKEYS, DV, 1.0f);
}

// round 12
// speedup vs baseline: 1.6180x; 1.6180x over previous
#include <cuda_runtime.h>
#include <math.h>
#include <stdint.h>

// Problem shapes (fixed by the dataset)
#define B_ROWS 16384
#define DK     512
#define NKEYS  4096
#define DV     512
#define NH     32
#define TAU_MIN 0.1f
#define TAU_MAX 5.0f
#define EPSF    1e-8f

// Scratch (never passed from host — selector/sentinel resolution in device code)
__device__ float g_logits[(size_t)B_ROWS * NKEYS];   // logits / attn scratch
__device__ float g_q [(size_t)B_ROWS * DK];          // tf32-rounded Q
__device__ float g_k [(size_t)NKEYS  * DK];          // tf32-rounded keys
__device__ float g_vt[(size_t)DV * NKEYS];           // tf32-rounded V^T

// ---------------------------------------------------------------------------
// helpers
// ---------------------------------------------------------------------------
__device__ __forceinline__ float round_tf32(float v) {
    uint32_t r;
    asm("cvt.rna.tf32.f32 %0, %1;" : "=r"(r) : "f"(v));
    return __uint_as_float(r);
}
__device__ __forceinline__ void mma_tf32(float* c, const uint32_t* a, const uint32_t* b) {
    asm volatile(
        "mma.sync.aligned.m16n8k8.row.col.f32.tf32.tf32.f32 "
        "{%0,%1,%2,%3}, {%4,%5,%6,%7}, {%8,%9}, {%0,%1,%2,%3};"
        : "+f"(c[0]), "+f"(c[1]), "+f"(c[2]), "+f"(c[3])
        : "r"(a[0]), "r"(a[1]), "r"(a[2]), "r"(a[3]), "r"(b[0]), "r"(b[1]));
}
__device__ __forceinline__ void cp_async16(uint32_t saddr, const void* gptr) {
    asm volatile("cp.async.ca.shared.global [%0], [%1], 16;" :: "r"(saddr), "l"(gptr));
}
#define CP_COMMIT() asm volatile("cp.async.commit_group;" ::: "memory")
#define CP_WAIT2()  asm volatile("cp.async.wait_group 2;" ::: "memory")

// ---------------------------------------------------------------------------
// tf32 mma GEMM with 4-stage cp.async pipeline.
// C[M,N] = alpha * A[M,K] @ B[N,K]^T ; operands pre-rounded to tf32 grid.
// CTA tile 128x128, BK=16, 256 threads (8 warps 4x2), warp tile 32x64.
// sel==1: A=g_q, B=g_k, C=g_logits (GEMM1).
// sel==2: B=g_vt; A=g_logits if A==nullptr; C as given (GEMM2).
// ---------------------------------------------------------------------------
#define BK 16
#define LDSW 20                     // 16 data + 4 pad words
#define STAGE_W (128 * LDSW)        // words per stage per matrix
#define STAGES 4
#define GEMM_SMEM (2 * STAGES * STAGE_W * 4)   // 81920 B

__global__ __launch_bounds__(256, 2) void mma_gemm_kernel(
    const float* __restrict__ A, float* __restrict__ C,
    int K, int ldc, float alpha, int sel)
{
    const float* Bm;
    if (sel == 1) { A = g_q; Bm = g_k; C = g_logits; }
    else          { Bm = g_vt; if (A == nullptr) A = g_logits; }

    extern __shared__ float smem[];
    float* As = smem;                       // [STAGES][STAGE_W]
    float* Bs = smem + STAGES * STAGE_W;
    const uint32_t sA = (uint32_t)__cvta_generic_to_shared(As);
    const uint32_t sB = (uint32_t)__cvta_generic_to_shared(Bs);

    const int tid  = threadIdx.x;
    const int wid  = tid >> 5;
    const int lane = tid & 31;
    const int gid  = lane >> 2;
    const int tig  = lane & 3;
    const int m0w  = (wid >> 1) * 32;
    const int n0w  = (wid & 1) * 64;
    const int bm0  = blockIdx.y * 128;
    const int bn0  = blockIdx.x * 128;

    const int grow = tid >> 2;            // 0..63
    const int gkc  = (tid & 3) * 4;       // 0,4,8,12

    const float* Ar0 = A  + (size_t)(bm0 + grow) * K + gkc;
    const float* Ar1 = Ar0 + (size_t)64 * K;
    const float* Br0 = Bm + (size_t)(bn0 + grow) * K + gkc;
    const float* Br1 = Br0 + (size_t)64 * K;
    const uint32_t so0 = (uint32_t)(grow * LDSW + gkc) * 4;
    const uint32_t so1 = (uint32_t)((grow + 64) * LDSW + gkc) * 4;

    float acc[2][8][4];
#pragma unroll
    for (int mi = 0; mi < 2; mi++)
#pragma unroll
        for (int ni = 0; ni < 8; ni++)
#pragma unroll
            for (int c = 0; c < 4; c++) acc[mi][ni][c] = 0.f;

    const int niter = K / BK;

    // prologue: issue stages 0..STAGES-2
#pragma unroll
    for (int s = 0; s < STAGES - 1; ++s) {
        if (s < niter) {
            const int k0 = s * BK;
            const uint32_t ob = (uint32_t)(s * STAGE_W) * 4;
            cp_async16(sA + ob + so0, Ar0 + k0);
            cp_async16(sA + ob + so1, Ar1 + k0);
            cp_async16(sB + ob + so0, Br0 + k0);
            cp_async16(sB + ob + so1, Br1 + k0);
        }
        CP_COMMIT();
    }

    for (int it = 0; it < niter; ++it) {
        CP_WAIT2();
        __syncthreads();

        // issue tile it+STAGES-1 into the buffer freed at iter it-1
        const int nt = it + STAGES - 1;
        if (nt < niter) {
            const int k0 = nt * BK;
            const uint32_t ob = (uint32_t)((nt % STAGES) * STAGE_W) * 4;
            cp_async16(sA + ob + so0, Ar0 + k0);
            cp_async16(sA + ob + so1, Ar1 + k0);
            cp_async16(sB + ob + so0, Br0 + k0);
            cp_async16(sB + ob + so1, Br1 + k0);
        }
        CP_COMMIT();

        // compute on current buffer (proven R10 fragment code)
        const uint32_t* Ab = (const uint32_t*)(As + (it % STAGES) * STAGE_W);
        const uint32_t* Bb = (const uint32_t*)(Bs + (it % STAGES) * STAGE_W);
#pragma unroll
        for (int ks = 0; ks < 2; ks++) {
            const int kk = ks * 8 + tig;
            uint32_t a[2][4];
#pragma unroll
            for (int mi = 0; mi < 2; mi++) {
                int r = m0w + mi * 16 + gid;
                a[mi][0] = Ab[r * LDSW + kk];
                a[mi][1] = Ab[(r + 8) * LDSW + kk];
                a[mi][2] = Ab[r * LDSW + kk + 4];
                a[mi][3] = Ab[(r + 8) * LDSW + kk + 4];
            }
#pragma unroll
            for (int ni = 0; ni < 8; ni++) {
                int c = n0w + ni * 8 + gid;
                uint32_t bb[2] = { Bb[c * LDSW + kk], Bb[c * LDSW + kk + 4] };
#pragma unroll
                for (int mi = 0; mi < 2; mi++)
                    mma_tf32(acc[mi][ni], a[mi], bb);
            }
        }
    }

    // epilogue
#pragma unroll
    for (int mi = 0; mi < 2; mi++) {
        const int row0 = bm0 + m0w + mi * 16 + gid;
#pragma unroll
        for (int ni = 0; ni < 8; ni++) {
            const int col = bn0 + n0w + ni * 8 + tig * 2;
            float2 v0 = make_float2(alpha * acc[mi][ni][0], alpha * acc[mi][ni][1]);
            float2 v1 = make_float2(alpha * acc[mi][ni][2], alpha * acc[mi][ni][3]);
            *(float2*)&C[(size_t)row0 * ldc + col]       = v0;
            *(float2*)&C[(size_t)(row0 + 8) * ldc + col] = v1;
        }
    }
}

// ---------------------------------------------------------------------------
// Pre-round Q and keys to tf32 grid (enables raw-bit cp.async staging)
// ---------------------------------------------------------------------------
__global__ void preround_kernel(const float* __restrict__ q,
                                const float* __restrict__ keys)
{
    const size_t nq = (size_t)B_ROWS * DK / 4;
    const size_t nk = (size_t)NKEYS * DK / 4;
    const size_t stride = (size_t)gridDim.x * blockDim.x;
    for (size_t i = blockIdx.x * (size_t)blockDim.x + threadIdx.x;
         i < nq; i += stride) {
        float4 v = ((const float4*)q)[i];
        v.x = round_tf32(v.x); v.y = round_tf32(v.y);
        v.z = round_tf32(v.z); v.w = round_tf32(v.w);
        ((float4*)g_q)[i] = v;
    }
    for (size_t i = blockIdx.x * (size_t)blockDim.x + threadIdx.x;
         i < nk; i += stride) {
        float4 v = ((const float4*)keys)[i];
        v.x = round_tf32(v.x); v.y = round_tf32(v.y);
        v.z = round_tf32(v.z); v.w = round_tf32(v.w);
        ((float4*)g_k)[i] = v;
    }
}

// ---------------------------------------------------------------------------
// V transpose with tf32 rounding: g_vt[d, n] = round(V[n, d])
// ---------------------------------------------------------------------------
__global__ void transpose_v_kernel(const float* __restrict__ V)
{
    __shared__ float t[32][33];
    const int n0 = blockIdx.x * 32;
    const int d0 = blockIdx.y * 32;
    const int x = threadIdx.x, y = threadIdx.y;
#pragma unroll
    for (int yy = y; yy < 32; yy += 8)
        t[yy][x] = V[(size_t)(n0 + yy) * DV + d0 + x];
    __syncthreads();
#pragma unroll
    for (int yy = y; yy < 32; yy += 8)
        g_vt[(size_t)(d0 + yy) * NKEYS + n0 + x] = round_tf32(t[x][yy]);
}

// ---------------------------------------------------------------------------
// FUSED per-row pass: one logits read; entropy -> MLP -> tau -> tau-softmax.
// attn output stored tf32-rounded (GEMM2 A operand).
// ---------------------------------------------------------------------------
__device__ __forceinline__ void mzs_combine(float& m, float& Z, float& S,
                                            float m2, float Z2, float S2)
{
    float mn = fmaxf(m, m2);
    float e1 = __expf(m - mn);
    float e2 = __expf(m2 - mn);
    Z = Z * e1 + Z2 * e2;
    S = S * e1 + S2 * e2;
    m = mn;
}

__global__ __launch_bounds__(256) void fused_row_kernel(
    const float* __restrict__ w1, const float* __restrict__ b1,
    const float* __restrict__ w2, const float* __restrict__ b2,
    float* __restrict__ attn_out, float* __restrict__ ent_out,
    float* __restrict__ tau_out)
{
    __shared__ float sw[NKEYS];
    __shared__ float sred[8];
    __shared__ float sbc[2];
    __shared__ float smr[8], szr[8], ssr[8];

    if (attn_out == nullptr) attn_out = g_logits;
    const int row = blockIdx.x;
    const int tid = threadIdx.x;
    const float4* c4 = (const float4*)(g_logits + (size_t)row * NKEYS);
    float4* s4 = (float4*)sw;

    float m = -INFINITY, Z = 0.f, S = 0.f;
#pragma unroll
    for (int i = 0; i < 4; i++) {
        const int j = tid + i * 256;
        float4 v = c4[j];
        s4[j] = v;
        float f[4] = {v.x, v.y, v.z, v.w};
#pragma unroll
        for (int e = 0; e < 4; e++) {
            float l = f[e];
            if (l > m) {
                float sc = __expf(m - l);
                Z *= sc; S *= sc; m = l;
            }
            float ex = __expf(l - m);
            Z += ex;
            S += ex * l;
        }
    }
#pragma unroll
    for (int off = 16; off; off >>= 1) {
        float m2 = __shfl_down_sync(0xffffffffu, m, off);
        float Z2 = __shfl_down_sync(0xffffffffu, Z, off);
        float S2 = __shfl_down_sync(0xffffffffu, S, off);
        mzs_combine(m, Z, S, m2, Z2, S2);
    }
    const int wid = tid >> 5, lane = tid & 31;
    if (lane == 0) { smr[wid] = m; szr[wid] = Z; ssr[wid] = S; }
    __syncthreads();

    if (tid == 0) {
        m = smr[0]; Z = szr[0]; S = ssr[0];
#pragma unroll
        for (int w = 1; w < 8; w++) mzs_combine(m, Z, S, smr[w], szr[w], ssr[w]);

        float H = m + logf(Z) - S / Z - (float)NKEYS * EPSF;
        float max_entropy = logf((float)NKEYS);
        float e = H / (max_entropy + EPSF);
        e = fminf(fmaxf(e, 0.f), 1.f);

        float acc2 = b2[0];
#pragma unroll
        for (int h = 0; h < NH; h++) {
            float z1 = e * w1[h] + b1[h];
            float g  = 0.5f * z1 * (1.f + erff(z1 * 0.70710678118654752f));
            acc2 += g * w2[h];
        }
        float sc  = 1.f / (1.f + expf(-acc2));
        float tau = TAU_MIN + (TAU_MAX - TAU_MIN) * sc;

        if (ent_out) ent_out[row] = e;
        if (tau_out) tau_out[row] = tau;
        sbc[0] = m;
        sbc[1] = 1.f / (tau + EPSF);
    }
    __syncthreads();

    const float mm   = sbc[0];
    const float itau = sbc[1];
    float z = 0.f;
#pragma unroll
    for (int i = 0; i < 4; i++) {
        const int j = tid + i * 256;
        float4 v = s4[j];
        v.x = __expf((v.x - mm) * itau);
        v.y = __expf((v.y - mm) * itau);
        v.z = __expf((v.z - mm) * itau);
        v.w = __expf((v.w - mm) * itau);
        s4[j] = v;
        z += v.x + v.y + v.z + v.w;
    }
#pragma unroll
    for (int off = 16; off; off >>= 1)
        z += __shfl_down_sync(0xffffffffu, z, off);
    if (lane == 0) sred[wid] = z;
    __syncthreads();
    if (tid == 0) {
        float t = 0.f;
#pragma unroll
        for (int w = 0; w < 8; w++) t += sred[w];
        sred[0] = 1.f / t;
    }
    __syncthreads();
    const float invz = sred[0];

    float4* o4 = (float4*)(attn_out + (size_t)row * NKEYS);
#pragma unroll
    for (int i = 0; i < 4; i++) {
        const int j = tid + i * 256;
        float4 v = s4[j];
        v.x = round_tf32(v.x * invz);
        v.y = round_tf32(v.y * invz);
        v.z = round_tf32(v.z * invz);
        v.w = round_tf32(v.w * invz);
        o4[j] = v;
    }
}

// ---------------------------------------------------------------------------
extern "C" void kernel_launch(void* const* d_in, const int* in_sizes, int n_in,
                              void* d_out, int out_size)
{
    const float* q      = (const float*)d_in[0];
    const float* keys   = (const float*)d_in[1];
    const float* values = (const float*)d_in[2];
    const float* w1     = (const float*)d_in[3];
    const float* b1     = (const float*)d_in[4];
    const float* w2     = (const float*)d_in[5];
    const float* b2     = (const float*)d_in[6];
    float* out = (float*)d_out;

    const size_t sz_o    = (size_t)B_ROWS * DV;
    const size_t sz_attn = (size_t)B_ROWS * NKEYS;
    const size_t full_sz = sz_o + sz_attn + 2 * (size_t)B_ROWS;
    const bool full = ((size_t)out_size >= full_sz);

    float* out_o    = out;
    float* out_attn = full ? out + sz_o : nullptr;           // nullptr -> scratch
    float* out_ent  = full ? out + sz_o + sz_attn : nullptr;
    float* out_tau  = full ? out_ent + B_ROWS : nullptr;

    const float base_scale = 0.044194173824159216f;          // 512^-0.5

    // unconditional (no static guards); capture-safe non-stream API
    cudaFuncSetAttribute(mma_gemm_kernel,
                         cudaFuncAttributeMaxDynamicSharedMemorySize, GEMM_SMEM);

    // 0a) pre-round Q, keys to tf32 grid
    preround_kernel<<<1024, 256>>>(q, keys);
    // 0b) transpose + round V -> g_vt
    transpose_v_kernel<<<dim3(NKEYS / 32, DV / 32), dim3(32, 8)>>>(values);

    // 1) scaled logits -> g_logits  (sel=1: g_q @ g_k^T)
    mma_gemm_kernel<<<dim3(NKEYS / 128, B_ROWS / 128), 256, GEMM_SMEM>>>(
        nullptr, nullptr, DK, NKEYS, base_scale, 1);

    // 2+3) fused entropy + tau + tau-softmax (one logits read)
    fused_row_kernel<<<B_ROWS, 256>>>(w1, b1, w2, b2, out_attn, out_ent, out_tau);

    // 4) output = attn @ V  (sel=2: B=g_vt; A=out_attn or scratch)
    const float* attn_src = full ? out_attn : nullptr;
    mma_gemm_kernel<<<dim3(DV / 128, B_ROWS / 128), 256, GEMM_SMEM>>>(
        attn_src, out_o, NKEYS, DV, 1.0f, 2);
}